// round 10
// baseline (speedup 1.0000x reference)
#include <cuda_runtime.h>
#include <cuda_bf16.h>

#define VOCAB 100000
#define EMB   300
#define BSZ   2048
#define SEQL  200
#define HID   128
#define OUTD  20

#define EMB4   (EMB / 4)         // 75 float4 per row
#define SPB2   4                 // samples per MLP block
#define DCH    10                // d-chunks of exactly 30 rows (10*30=300)
#define MLPT   320               // MLP block threads = 32 jg x 10 c

#define NCHUNK 4
#define SCHUNK (BSZ / NCHUNK)                  // 512 samples per chunk
#define GBLK   ((SCHUNK * EMB4) / 256)         // 150 gather blocks per chunk
#define MBLK   (SCHUNK / SPB2)                 // 128 MLP blocks per chunk

// rep scratch (device global — no allocation allowed)
__device__ float4 g_rep4[BSZ * EMB4];

// ---------------------------------------------------------------------------
// Kernel 1: embedding-bag mean for one sample chunk.  Per-thread code is the
// proven LTS-cap config (R3) — only a sample-base offset added.
// ---------------------------------------------------------------------------
__global__ __launch_bounds__(256) void gather_kernel(
    const int*    __restrict__ x,        // [B, L]
    const int*    __restrict__ lengths,  // [B]
    const float4* __restrict__ emb4,     // [VOCAB, 75]
    int b_base)
{
    const int gid = blockIdx.x * 256 + threadIdx.x;    // within chunk
    const int b = b_base + gid / EMB4;
    const int d = gid % EMB4;

    const int4* xb4 = (const int4*)(x + (size_t)b * SEQL);

    float4 a0 = make_float4(0.f, 0.f, 0.f, 0.f);
    float4 a1 = a0, a2 = a0, a3 = a0, a4 = a0, a5 = a0, a6 = a0, a7 = a0;

    #pragma unroll 1
    for (int it = 0; it < 25; ++it) {
        const int4 ia = __ldg(xb4 + it * 2 + 0);
        const int4 ib = __ldg(xb4 + it * 2 + 1);
        const float4 v0 = __ldg(emb4 + (size_t)ia.x * EMB4 + d);
        const float4 v1 = __ldg(emb4 + (size_t)ia.y * EMB4 + d);
        const float4 v2 = __ldg(emb4 + (size_t)ia.z * EMB4 + d);
        const float4 v3 = __ldg(emb4 + (size_t)ia.w * EMB4 + d);
        const float4 v4 = __ldg(emb4 + (size_t)ib.x * EMB4 + d);
        const float4 v5 = __ldg(emb4 + (size_t)ib.y * EMB4 + d);
        const float4 v6 = __ldg(emb4 + (size_t)ib.z * EMB4 + d);
        const float4 v7 = __ldg(emb4 + (size_t)ib.w * EMB4 + d);
        a0.x += v0.x; a0.y += v0.y; a0.z += v0.z; a0.w += v0.w;
        a1.x += v1.x; a1.y += v1.y; a1.z += v1.z; a1.w += v1.w;
        a2.x += v2.x; a2.y += v2.y; a2.z += v2.z; a2.w += v2.w;
        a3.x += v3.x; a3.y += v3.y; a3.z += v3.z; a3.w += v3.w;
        a4.x += v4.x; a4.y += v4.y; a4.z += v4.z; a4.w += v4.w;
        a5.x += v5.x; a5.y += v5.y; a5.z += v5.z; a5.w += v5.w;
        a6.x += v6.x; a6.y += v6.y; a6.z += v6.z; a6.w += v6.w;
        a7.x += v7.x; a7.y += v7.y; a7.z += v7.z; a7.w += v7.w;
    }

    const float inv = 1.0f / (float)__ldg(lengths + b);
    float4 r;
    r.x = (a0.x + a1.x + a2.x + a3.x + a4.x + a5.x + a6.x + a7.x) * inv;
    r.y = (a0.y + a1.y + a2.y + a3.y + a4.y + a5.y + a6.y + a7.y) * inv;
    r.z = (a0.z + a1.z + a2.z + a3.z + a4.z + a5.z + a6.z + a7.z) * inv;
    r.w = (a0.w + a1.w + a2.w + a3.w + a4.w + a5.w + a6.w + a7.w) * inv;
    g_rep4[(size_t)b * EMB4 + d] = r;
}

// ---------------------------------------------------------------------------
// Kernel 2: logits = relu(rep @ W1 + b1) @ W2 + b2 for one sample chunk.
// R9's branch-free fully-unrolled GEMM1 (best measured MLP).
// ---------------------------------------------------------------------------
__global__ __launch_bounds__(MLPT) void mlp_kernel(
    const float* __restrict__ W1,   // [EMB, HID]
    const float* __restrict__ b1,   // [HID]
    const float* __restrict__ W2,   // [HID, OUTD]
    const float* __restrict__ b2,   // [OUTD]
    float*       __restrict__ out,  // [B, OUTD]
    int b_base)
{
    __shared__ __align__(16) float repT[EMB][SPB2];         // 4.8 KB
    __shared__ __align__(16) float hpart[DCH][SPB2][HID];   // 20 KB
    __shared__ float hbuf[SPB2][HID];                       // 2 KB

    const int tid = threadIdx.x;
    const int b0  = b_base + blockIdx.x * SPB2;

    // ---- load rep tile ------------------------------------------------------
    if (tid < SPB2 * EMB4) {
        const int s = tid / EMB4;
        const int d = tid - s * EMB4;
        const float4 v = g_rep4[(size_t)(b0 + s) * EMB4 + d];
        repT[4 * d + 0][s] = v.x;
        repT[4 * d + 1][s] = v.y;
        repT[4 * d + 2][s] = v.z;
        repT[4 * d + 3][s] = v.w;
    }
    __syncthreads();

    // ---- GEMM1: warp = d-chunk (30 rows), lane = 4-col group ---------------
    {
        const int jg = tid & 31;
        const int c  = tid >> 5;
        const int d0 = c * 30;

        float4 acc[SPB2];
        #pragma unroll
        for (int s = 0; s < SPB2; ++s) acc[s] = make_float4(0.f, 0.f, 0.f, 0.f);

        const float4* W14 = (const float4*)W1;

        float4 w = __ldg(&W14[(size_t)d0 * 32 + jg]);
        float4 r = *(const float4*)&repT[d0][0];

        #pragma unroll
        for (int k = 0; k < 30; ++k) {
            const float4 wc = w;
            const float4 rc = r;
            const int dn = d0 + ((k + 1) % 30);
            w = __ldg(&W14[(size_t)dn * 32 + jg]);
            r = *(const float4*)&repT[dn][0];
            acc[0].x += rc.x * wc.x; acc[0].y += rc.x * wc.y; acc[0].z += rc.x * wc.z; acc[0].w += rc.x * wc.w;
            acc[1].x += rc.y * wc.x; acc[1].y += rc.y * wc.y; acc[1].z += rc.y * wc.z; acc[1].w += rc.y * wc.w;
            acc[2].x += rc.z * wc.x; acc[2].y += rc.z * wc.y; acc[2].z += rc.z * wc.z; acc[2].w += rc.z * wc.w;
            acc[3].x += rc.w * wc.x; acc[3].y += rc.w * wc.y; acc[3].z += rc.w * wc.z; acc[3].w += rc.w * wc.w;
        }

        #pragma unroll
        for (int s = 0; s < SPB2; ++s)
            *(float4*)&hpart[c][s][4 * jg] = acc[s];
    }
    __syncthreads();

    // ---- combine partials + bias + relu ------------------------------------
    for (int i = tid; i < SPB2 * HID; i += MLPT) {
        const int s = i >> 7;
        const int j = i & (HID - 1);
        float v = __ldg(&b1[j]);
        #pragma unroll
        for (int c = 0; c < DCH; ++c) v += hpart[c][s][j];
        hbuf[s][j] = v > 0.0f ? v : 0.0f;
    }
    __syncthreads();

    // ---- GEMM2 tail ---------------------------------------------------------
    if (tid < SPB2 * OUTD) {
        const int s = tid / OUTD;
        const int o = tid - s * OUTD;
        float a0 = __ldg(&b2[o]), a1 = 0.f, a2 = 0.f, a3 = 0.f;
        #pragma unroll 4
        for (int k = 0; k < HID; k += 4) {
            a0 += hbuf[s][k + 0] * __ldg(&W2[(size_t)(k + 0) * OUTD + o]);
            a1 += hbuf[s][k + 1] * __ldg(&W2[(size_t)(k + 1) * OUTD + o]);
            a2 += hbuf[s][k + 2] * __ldg(&W2[(size_t)(k + 2) * OUTD + o]);
            a3 += hbuf[s][k + 3] * __ldg(&W2[(size_t)(k + 3) * OUTD + o]);
        }
        out[(size_t)(b0 + s) * OUTD + o] = (a0 + a1) + (a2 + a3);
    }
}

// ---------------------------------------------------------------------------
// Host: chunked 2-stream pipeline.  Streams/events are process-lifetime
// handles created once (no device memory); the enqueued work is identical
// on every call, so replay determinism holds.
// ---------------------------------------------------------------------------
struct PipeRes {
    cudaStream_t s1, s2;
    cudaEvent_t  fork, join;
    cudaEvent_t  eg[NCHUNK];
    PipeRes() {
        cudaStreamCreateWithFlags(&s1, cudaStreamNonBlocking);
        cudaStreamCreateWithFlags(&s2, cudaStreamNonBlocking);
        cudaEventCreateWithFlags(&fork, cudaEventDisableTiming);
        cudaEventCreateWithFlags(&join, cudaEventDisableTiming);
        for (int c = 0; c < NCHUNK; ++c)
            cudaEventCreateWithFlags(&eg[c], cudaEventDisableTiming);
    }
};

extern "C" void kernel_launch(void* const* d_in, const int* in_sizes, int n_in,
                              void* d_out, int out_size)
{
    static PipeRes R;   // created on first (uncaptured correctness) call

    const int*    x       = (const int*)    d_in[0];
    const int*    lengths = (const int*)    d_in[1];
    const float4* emb4    = (const float4*) d_in[2];
    const float*  W1      = (const float*)  d_in[3];
    const float*  b1      = (const float*)  d_in[4];
    const float*  W2      = (const float*)  d_in[5];
    const float*  b2      = (const float*)  d_in[6];
    float*        out     = (float*)        d_out;

    // fork from the launch stream
    cudaEventRecord(R.fork, (cudaStream_t)0);
    cudaStreamWaitEvent(R.s1, R.fork, 0);

    // s1: gather chunks; s2: MLP chunk c after gather chunk c
    for (int c = 0; c < NCHUNK; ++c) {
        gather_kernel<<<GBLK, 256, 0, R.s1>>>(x, lengths, emb4, c * SCHUNK);
        cudaEventRecord(R.eg[c], R.s1);
    }
    for (int c = 0; c < NCHUNK; ++c) {
        cudaStreamWaitEvent(R.s2, R.eg[c], 0);
        mlp_kernel<<<MBLK, MLPT, 0, R.s2>>>(W1, b1, W2, b2, out, c * SCHUNK);
    }

    // join back to the launch stream
    cudaEventRecord(R.join, R.s2);
    cudaStreamWaitEvent((cudaStream_t)0, R.join, 0);
}

// round 11
// speedup vs baseline: 3.4632x; 3.4632x over previous
#include <cuda_runtime.h>
#include <cuda_bf16.h>

#define VOCAB 100000
#define EMB   300
#define BSZ   2048
#define SEQL  200
#define HID   128
#define OUTD  20

#define EMB4  (EMB / 4)          // 75 float4 per row
#define SPB2  4                  // samples per MLP block -> grid 512
#define DCH   10                 // d-chunks of exactly 30 rows (10*30=300)
#define MLPT  320                // MLP block threads = 32 jg x 10 c

// rep scratch (device global — no allocation allowed)
__device__ float4 g_rep4[BSZ * EMB4];

// ---------------------------------------------------------------------------
// Kernel 1: embedding-bag mean.  At the LTS cap (12.9 TB/s warm) — DO NOT
// TOUCH (R3 config; every variant tried was equal or worse).
// ---------------------------------------------------------------------------
__global__ __launch_bounds__(256) void gather_kernel(
    const int*    __restrict__ x,        // [B, L]
    const int*    __restrict__ lengths,  // [B]
    const float4* __restrict__ emb4)     // [VOCAB, 75]
{
    const int gid = blockIdx.x * 256 + threadIdx.x;
    if (gid >= BSZ * EMB4) return;
    const int b = gid / EMB4;
    const int d = gid - b * EMB4;

    const int4* xb4 = (const int4*)(x + (size_t)b * SEQL);

    float4 a0 = make_float4(0.f, 0.f, 0.f, 0.f);
    float4 a1 = a0, a2 = a0, a3 = a0, a4 = a0, a5 = a0, a6 = a0, a7 = a0;

    #pragma unroll 1
    for (int it = 0; it < 25; ++it) {
        const int4 ia = __ldg(xb4 + it * 2 + 0);
        const int4 ib = __ldg(xb4 + it * 2 + 1);
        const float4 v0 = __ldg(emb4 + (size_t)ia.x * EMB4 + d);
        const float4 v1 = __ldg(emb4 + (size_t)ia.y * EMB4 + d);
        const float4 v2 = __ldg(emb4 + (size_t)ia.z * EMB4 + d);
        const float4 v3 = __ldg(emb4 + (size_t)ia.w * EMB4 + d);
        const float4 v4 = __ldg(emb4 + (size_t)ib.x * EMB4 + d);
        const float4 v5 = __ldg(emb4 + (size_t)ib.y * EMB4 + d);
        const float4 v6 = __ldg(emb4 + (size_t)ib.z * EMB4 + d);
        const float4 v7 = __ldg(emb4 + (size_t)ib.w * EMB4 + d);
        a0.x += v0.x; a0.y += v0.y; a0.z += v0.z; a0.w += v0.w;
        a1.x += v1.x; a1.y += v1.y; a1.z += v1.z; a1.w += v1.w;
        a2.x += v2.x; a2.y += v2.y; a2.z += v2.z; a2.w += v2.w;
        a3.x += v3.x; a3.y += v3.y; a3.z += v3.z; a3.w += v3.w;
        a4.x += v4.x; a4.y += v4.y; a4.z += v4.z; a4.w += v4.w;
        a5.x += v5.x; a5.y += v5.y; a5.z += v5.z; a5.w += v5.w;
        a6.x += v6.x; a6.y += v6.y; a6.z += v6.z; a6.w += v6.w;
        a7.x += v7.x; a7.y += v7.y; a7.z += v7.z; a7.w += v7.w;
    }

    const float inv = 1.0f / (float)__ldg(lengths + b);
    float4 r;
    r.x = (a0.x + a1.x + a2.x + a3.x + a4.x + a5.x + a6.x + a7.x) * inv;
    r.y = (a0.y + a1.y + a2.y + a3.y + a4.y + a5.y + a6.y + a7.y) * inv;
    r.z = (a0.z + a1.z + a2.z + a3.z + a4.z + a5.z + a6.z + a7.z) * inv;
    r.w = (a0.w + a1.w + a2.w + a3.w + a4.w + a5.w + a6.w + a7.w) * inv;
    g_rep4[gid] = r;
}

// ---------------------------------------------------------------------------
// Kernel 2: logits = relu(rep @ W1 + b1) @ W2 + b2.
// R9 GEMM1 (branch-free, fully unrolled).  NEW: W2 staged in smem during the
// rep load; GEMM2 k-split across all 320 threads (no scalar-LDG tail).
// ---------------------------------------------------------------------------
__global__ __launch_bounds__(MLPT) void mlp_kernel(
    const float* __restrict__ W1,   // [EMB, HID]
    const float* __restrict__ b1,   // [HID]
    const float* __restrict__ W2,   // [HID, OUTD]
    const float* __restrict__ b2,   // [OUTD]
    float*       __restrict__ out)  // [B, OUTD]
{
    __shared__ __align__(16) float repT[EMB][SPB2];         // 4.8 KB
    __shared__ __align__(16) float hpart[DCH][SPB2][HID];   // 20 KB
    __shared__ float hbuf[SPB2][HID];                       // 2 KB
    __shared__ float W2s[HID * OUTD];                       // 10 KB
    __shared__ float g2part[4][SPB2][OUTD];                 // 1.25 KB

    const int tid = threadIdx.x;
    const int b0  = blockIdx.x * SPB2;

    // ---- stage W2 into smem (independent of rep; overlaps rep load) --------
    #pragma unroll
    for (int i = 0; i < (HID * OUTD + MLPT - 1) / MLPT; ++i) {
        const int idx = tid + i * MLPT;
        if (idx < HID * OUTD) W2s[idx] = __ldg(&W2[idx]);
    }

    // ---- load rep tile: 300 float4 loads, transpose into smem --------------
    if (tid < SPB2 * EMB4) {
        const int s = tid / EMB4;
        const int d = tid - s * EMB4;
        const float4 v = g_rep4[(size_t)(b0 + s) * EMB4 + d];
        repT[4 * d + 0][s] = v.x;
        repT[4 * d + 1][s] = v.y;
        repT[4 * d + 2][s] = v.z;
        repT[4 * d + 3][s] = v.w;
    }

    // ---- GEMM1 setup + W1 prefetch BEFORE the barrier (W1 indep of rep) ----
    const int jg = tid & 31;               // cols 4jg..4jg+3
    const int c  = tid >> 5;               // d-chunk 0..9
    const int d0 = c * 30;
    const float4* W14 = (const float4*)W1; // [EMB][32] float4
    float4 w = __ldg(&W14[(size_t)d0 * 32 + jg]);

    __syncthreads();

    // ---- GEMM1: warp = d-chunk (30 rows), lane = 4-col group ---------------
    {
        float4 acc[SPB2];
        #pragma unroll
        for (int s = 0; s < SPB2; ++s) acc[s] = make_float4(0.f, 0.f, 0.f, 0.f);

        float4 r = *(const float4*)&repT[d0][0];

        #pragma unroll
        for (int k = 0; k < 30; ++k) {
            const float4 wc = w;
            const float4 rc = r;
            const int dn = d0 + ((k + 1) % 30);      // compile-time; wraps to d0
            w = __ldg(&W14[(size_t)dn * 32 + jg]);   // prefetch next W1 row
            r = *(const float4*)&repT[dn][0];        // prefetch next rep row
            acc[0].x += rc.x * wc.x; acc[0].y += rc.x * wc.y; acc[0].z += rc.x * wc.z; acc[0].w += rc.x * wc.w;
            acc[1].x += rc.y * wc.x; acc[1].y += rc.y * wc.y; acc[1].z += rc.y * wc.z; acc[1].w += rc.y * wc.w;
            acc[2].x += rc.z * wc.x; acc[2].y += rc.z * wc.y; acc[2].z += rc.z * wc.z; acc[2].w += rc.z * wc.w;
            acc[3].x += rc.w * wc.x; acc[3].y += rc.w * wc.y; acc[3].z += rc.w * wc.z; acc[3].w += rc.w * wc.w;
        }

        #pragma unroll
        for (int s = 0; s < SPB2; ++s)
            *(float4*)&hpart[c][s][4 * jg] = acc[s];    // STS.128, conflict-free
    }
    __syncthreads();

    // ---- combine partials + bias + relu ------------------------------------
    for (int i = tid; i < SPB2 * HID; i += MLPT) {
        const int s = i >> 7;
        const int j = i & (HID - 1);
        float v = __ldg(&b1[j]);
        #pragma unroll
        for (int cc = 0; cc < DCH; ++cc) v += hpart[cc][s][j];
        hbuf[s][j] = v > 0.0f ? v : 0.0f;
    }
    __syncthreads();

    // ---- GEMM2, k-split over all 320 threads --------------------------------
    // pair p = tid % 80 -> (s = p/20, o = p%20); kc = tid / 80 (0..3, 32 k each)
    {
        const int p  = tid % 80;
        const int kc = tid / 80;
        const int s  = p / OUTD;
        const int o  = p - s * OUTD;
        const int k0 = kc * 32;

        float a0 = 0.f, a1 = 0.f, a2 = 0.f, a3 = 0.f;
        #pragma unroll
        for (int k = 0; k < 32; k += 4) {
            a0 += hbuf[s][k0 + k + 0] * W2s[(k0 + k + 0) * OUTD + o];
            a1 += hbuf[s][k0 + k + 1] * W2s[(k0 + k + 1) * OUTD + o];
            a2 += hbuf[s][k0 + k + 2] * W2s[(k0 + k + 2) * OUTD + o];
            a3 += hbuf[s][k0 + k + 3] * W2s[(k0 + k + 3) * OUTD + o];
        }
        g2part[kc][s][o] = (a0 + a1) + (a2 + a3);
    }
    __syncthreads();

    if (tid < SPB2 * OUTD) {
        const int s = tid / OUTD;
        const int o = tid - s * OUTD;
        out[(size_t)(b0 + s) * OUTD + o] = __ldg(&b2[o])
            + (g2part[0][s][o] + g2part[1][s][o])
            + (g2part[2][s][o] + g2part[3][s][o]);
    }
}

extern "C" void kernel_launch(void* const* d_in, const int* in_sizes, int n_in,
                              void* d_out, int out_size)
{
    const int*    x       = (const int*)    d_in[0];
    const int*    lengths = (const int*)    d_in[1];
    const float4* emb4    = (const float4*) d_in[2];
    const float*  W1      = (const float*)  d_in[3];
    const float*  b1      = (const float*)  d_in[4];
    const float*  W2      = (const float*)  d_in[5];
    const float*  b2      = (const float*)  d_in[6];
    float*        out     = (float*)        d_out;

    const int gather_items = BSZ * EMB4;                    // 153600
    gather_kernel<<<(gather_items + 255) / 256, 256>>>(x, lengths, emb4);
    mlp_kernel<<<BSZ / SPB2, MLPT>>>(W1, b1, W2, b2, out);  // 512 blocks
}